// round 17
// baseline (speedup 1.0000x reference)
#include <cuda_runtime.h>
#include <cuda_bf16.h>
#include <math.h>
#include <stdint.h>

#define BATCH 2048
#define SEQ   128
#define HID   512
#define TOUT  24
#define NTHR  512    // 16 warps: 8 m-tiles x 2 n-halves
#define GRID  128
#define NKT   32

// ---- global scratch ----
__device__ uint4 g_A[16][2][8][NKT][2][32];  // [grp][plane][mt][kt][hi/lo][lane]
__device__ float g_xT[SEQ][BATCH];           // transposed input
__device__ float g_part[2][16][8][128];      // fc partials (parity-buffered)
__device__ unsigned g_bar[16][32];           // group barrier counters
__device__ unsigned g_rst[16][32];           // reset counters

// ---- SMEM layout (bytes) ----
#define OFF_B    0         // resident B slice: 32kt x 8ntl x 32 x 16B = 131072
#define OFF_EPE  131072    // 32 float4
#define OFF_EPD  131584    // 32 float4
#define OFF_FC2  132096    // 32 float2
#define OFF_DINP 132352    // 128 f
#define OFF_RED  132864    // 2 x 128 f
#define OFF_HX   133888    // own-tile mirror: 2 planes x 8mt x 4ktl x 2 x 32 x 16B = 65536
#define SMEM_SZ  199424

__device__ __forceinline__ void mma_bf16(float* d, uint4 a, uint32_t b0, uint32_t b1) {
    asm volatile(
        "mma.sync.aligned.m16n8k16.row.col.f32.bf16.bf16.f32 "
        "{%0,%1,%2,%3}, {%4,%5,%6,%7}, {%8,%9}, {%0,%1,%2,%3};"
        : "+f"(d[0]), "+f"(d[1]), "+f"(d[2]), "+f"(d[3])
        : "r"(a.x), "r"(a.y), "r"(a.z), "r"(a.w), "r"(b0), "r"(b1));
}
__device__ __forceinline__ uint32_t pack_bf2(__nv_bfloat16 a, __nv_bfloat16 b) {
    __nv_bfloat162 t; t.x = a; t.y = b;
    return *reinterpret_cast<uint32_t*>(&t);
}
__device__ __forceinline__ void split2(float a, float b, uint32_t& hi, uint32_t& lo) {
    __nv_bfloat16 ah = __float2bfloat16(a);
    __nv_bfloat16 bh = __float2bfloat16(b);
    __nv_bfloat16 al = __float2bfloat16(a - __bfloat162float(ah));
    __nv_bfloat16 bl = __float2bfloat16(b - __bfloat162float(bh));
    hi = pack_bf2(ah, bh);
    lo = pack_bf2(al, bl);
}
// fast tanh on MUFU pipe: abs err ~2^-20
__device__ __forceinline__ float ftanh(float x) {
    float e = __expf(2.0f * x);
    return 1.0f - __fdividef(2.0f, e + 1.0f);
}

// Prologue: transpose x -> g_xT[s][b].
__global__ void transpose_x(const float* __restrict__ x) {
    __shared__ float tile[32][33];
    int bx = blockIdx.x * 32, sx = blockIdx.y * 32;
    int tx = threadIdx.x, ty = threadIdx.y;
    #pragma unroll
    for (int i = 0; i < 32; i += 8)
        tile[ty + i][tx] = x[(bx + ty + i) * SEQ + sx + tx];
    __syncthreads();
    #pragma unroll
    for (int i = 0; i < 32; i += 8)
        g_xT[sx + ty + i][bx + tx] = tile[tx][ty + i];
}

__global__ __launch_bounds__(NTHR, 1)
void rnn_kernel(const float* __restrict__ eWhh, const float* __restrict__ dWhh,
                const float* __restrict__ eWih,
                const float* __restrict__ ebih, const float* __restrict__ ebhh,
                const float* __restrict__ dWih,
                const float* __restrict__ dbih, const float* __restrict__ dbhh,
                const float* __restrict__ fcW, const float* __restrict__ fcb,
                float* __restrict__ out)
{
    extern __shared__ char smem[];
    const int tid  = threadIdx.x;
    const int wid  = tid >> 5, lane = tid & 31;
    const int gid  = lane >> 2, tig = lane & 3;
    const int g    = blockIdx.x >> 3, s = blockIdx.x & 7;
    const int b0   = g * 128, n0 = s * 64, s4 = s * 4;
    const int mt   = wid & 7, nhf = wid >> 3;
    const int r0   = mt * 16 + gid, r1 = r0 + 8;

    const uint4* smB  = (const uint4*)(smem + OFF_B);
    uint4*       smBw = (uint4*)(smem + OFF_B);
    float4* epE  = (float4*)(smem + OFF_EPE);
    float4* epD  = (float4*)(smem + OFF_EPD);
    float2* fc2  = (float2*)(smem + OFF_FC2);
    float*  dinp = (float*)(smem + OFF_DINP);
    float*  red  = (float*)(smem + OFF_RED);
    uint4*  smHX = (uint4*)(smem + OFF_HX);   // [plane][mt][ktl][hilo][lane]

    // ---- epilogue tables ----
    if (tid < 32) {
        int c0 = n0 + 2 * tid, c1 = c0 + 1;
        epE[tid] = make_float4(eWih[c0], eWih[c1],
                               ebih[c0] + ebhh[c0], ebih[c1] + ebhh[c1]);
        epD[tid] = make_float4(dWih[c0], dWih[c1],
                               dbih[c0] + dbhh[c0], dbih[c1] + dbhh[c1]);
        fc2[tid] = make_float2(fcW[c0], fcW[c1]);
    }
    const float fcb0 = fcb[0];

    // ---- pack this CTA's 64-col Whh slice into fragment-ordered bf16 hi/lo ----
    auto packB = [&](const float* __restrict__ W) {
        #pragma unroll 1
        for (int i = 0; i < 16; i++) {
            int e = tid + i * NTHR;
            int lane2 = e & 31, ntl = (e >> 5) & 7, kt = e >> 8;
            int n = n0 + ntl * 8 + (lane2 >> 2);
            int k = kt * 16 + 2 * (lane2 & 3);
            const float* r = W + n * HID + k;
            float2 a = *(const float2*)r;
            float2 b = *(const float2*)(r + 8);
            uint32_t b0h, b0l, b1h, b1l;
            split2(a.x, a.y, b0h, b0l);
            split2(b.x, b.y, b1h, b1l);
            smBw[e] = make_uint4(b0h, b1h, b0l, b1l);
        }
    };

    packB(eWhh);
    // zero own g_A plane-0 partition + SMEM mirror plane 0 (h0 = 0)
    {
        uint4* az = &g_A[g][0][s][0][0][0];
        for (int i = tid; i < 2048; i += NTHR) az[i] = make_uint4(0, 0, 0, 0);
        for (int i = tid; i < 2048; i += NTHR) smHX[i] = make_uint4(0, 0, 0, 0);
    }

    unsigned ph = 0;
    volatile unsigned* barp = &g_bar[g][0];
    auto arrive = [&]() {
        __syncthreads();
        if (tid == 0) {
            __threadfence();
            atomicAdd(&g_bar[g][0], 1u);
        }
    };
    auto wait_flag = [&]() {
        ph++;
        const unsigned tgt = 8u * ph;
        if (lane == 0) {
            while (*barp < tgt) { }
            __threadfence();
        }
        __syncwarp();
    };

    arrive();   // publish zeros (and ensure smB pack + mirror init done CTA-wide)

    // Own h fragments (this warp's 2 k-tiles: ktl = nhf*2 + {0,1}) in registers.
    uint4 own_h[2], own_l[2];
    #pragma unroll
    for (int i = 0; i < 2; i++) {
        own_h[i] = make_uint4(0, 0, 0, 0);
        own_l[i] = make_uint4(0, 0, 0, 0);
    }

    float acc[4][4];

    // consume one k-tile: 4 n-tiles (this warp's half) x 3 terms.
    auto consume = [&](int kt, uint4 ah, uint4 al) {
        const uint4* bp = smB + kt * 256 + nhf * 128 + lane;
        uint4 b0 = bp[0], b1 = bp[32], b2 = bp[64], b3 = bp[96];
        mma_bf16(acc[0], ah, b0.x, b0.y); mma_bf16(acc[1], ah, b1.x, b1.y);
        mma_bf16(acc[2], ah, b2.x, b2.y); mma_bf16(acc[3], ah, b3.x, b3.y);
        mma_bf16(acc[0], al, b0.x, b0.y); mma_bf16(acc[1], al, b1.x, b1.y);
        mma_bf16(acc[2], al, b2.x, b2.y); mma_bf16(acc[3], al, b3.x, b3.y);
        mma_bf16(acc[0], ah, b0.z, b0.w); mma_bf16(acc[1], ah, b1.z, b1.w);
        mma_bf16(acc[2], ah, b2.z, b2.w); mma_bf16(acc[3], ah, b3.z, b3.w);
    };

    // kloop: own 2 kt from regs cover the barrier wait; foreign prefetch issued
    // at wait resolution; partner 2 kt from SMEM mirror (29-cyc LDS) cover the
    // foreign refill; then 28 foreign kt via depth-4 __ldcg register pipeline.
    auto kloop = [&](const uint4* __restrict__ base, int pl) {
        #pragma unroll
        for (int i = 0; i < 4; i++)
            #pragma unroll
            for (int j = 0; j < 4; j++) acc[i][j] = 0.f;
        const int ko = s4 + nhf * 2;            // own kt base
        const int kp = s4 + (1 - nhf) * 2;      // partner kt base
        consume(ko,     own_h[0], own_l[0]);
        consume(ko + 1, own_h[1], own_l[1]);
        wait_flag();
        // issue foreign prefetch immediately (latency runs under partner consumes)
        uint4 ph_[4], pl_[4];
        #pragma unroll
        for (int u = 0; u < 4; u++) {
            int kt = (s4 + 4 + u) & 31;
            ph_[u] = __ldcg(base + kt * 64 + lane);
            pl_[u] = __ldcg(base + kt * 64 + 32 + lane);
        }
        // partner tiles from SMEM mirror (written by partner warp's epi, ordered
        // by arrive's __syncthreads)
        const uint4* px = smHX + pl * 2048 + mt * 256 + ((1 - nhf) * 2) * 64;
        uint4 qh0 = px[lane],      ql0 = px[32 + lane];
        uint4 qh1 = px[64 + lane], ql1 = px[96 + lane];
        consume(kp,     qh0, ql0);
        consume(kp + 1, qh1, ql1);
        #pragma unroll 1
        for (int j = 0; j < 6; j++) {
            #pragma unroll
            for (int u = 0; u < 4; u++) {
                int idx = 4 + j * 4 + u;
                int kt = (s4 + idx) & 31;
                uint4 ah = ph_[u], al = pl_[u];
                int nk = (s4 + idx + 4) & 31;
                ph_[u] = __ldcg(base + nk * 64 + lane);
                pl_[u] = __ldcg(base + nk * 64 + 32 + lane);
                consume(kt, ah, al);
            }
        }
        #pragma unroll
        for (int u = 0; u < 4; u++)
            consume((s4 + 28 + u) & 31, ph_[u], pl_[u]);
    };

    // epilogue: h = ftanh(acc + xv*wih + bias); own 2 kt -> regs + g_A + mirror.
    auto epi = [&](float xv0, float xv1, const float4* __restrict__ ep,
                   uint4* __restrict__ gAw, int np, bool dec) {
        float p0 = 0.f, p1 = 0.f;
        uint4 nh_[2], nl_[2];
        #pragma unroll
        for (int j = 0; j < 4; j++) {
            int pp = 16 * nhf + 4 * j + tig;
            float4 co = ep[pp];
            float h00 = ftanh(acc[j][0] + xv0 * co.x + co.z);
            float h01 = ftanh(acc[j][1] + xv0 * co.y + co.w);
            float h10 = ftanh(acc[j][2] + xv1 * co.x + co.z);
            float h11 = ftanh(acc[j][3] + xv1 * co.y + co.w);
            if (dec) {
                float2 f = fc2[pp];
                p0 = fmaf(h00, f.x, fmaf(h01, f.y, p0));
                p1 = fmaf(h10, f.x, fmaf(h11, f.y, p1));
            }
            int ktl = j >> 1;
            if ((j & 1) == 0) {
                split2(h00, h01, nh_[ktl].x, nl_[ktl].x);
                split2(h10, h11, nh_[ktl].y, nl_[ktl].y);
            } else {
                split2(h00, h01, nh_[ktl].z, nl_[ktl].z);
                split2(h10, h11, nh_[ktl].w, nl_[ktl].w);
            }
        }
        #pragma unroll
        for (int ktl = 0; ktl < 2; ktl++) {
            own_h[ktl] = nh_[ktl];
            own_l[ktl] = nl_[ktl];
            int kt = s4 + nhf * 2 + ktl;
            gAw[kt * 64 + lane]      = nh_[ktl];
            gAw[kt * 64 + 32 + lane] = nl_[ktl];
            uint4* hx = smHX + np * 2048 + mt * 256 + (nhf * 2 + ktl) * 64;
            hx[lane]      = nh_[ktl];
            hx[32 + lane] = nl_[ktl];
        }
        if (dec) {
            p0 += __shfl_xor_sync(0xffffffffu, p0, 1);
            p0 += __shfl_xor_sync(0xffffffffu, p0, 2);
            p1 += __shfl_xor_sync(0xffffffffu, p1, 1);
            p1 += __shfl_xor_sync(0xffffffffu, p1, 2);
            if (tig == 0) {
                red[nhf * 128 + r0] = p0;
                red[nhf * 128 + r1] = p1;
            }
        }
    };

    const uint4* gAr[2] = { &g_A[g][0][mt][0][0][0], &g_A[g][1][mt][0][0][0] };
    uint4*       gAw[2] = { &g_A[g][0][mt][0][0][0], &g_A[g][1][mt][0][0][0] };

    // ---- encoder: 128 steps ----
    #pragma unroll 1
    for (int t = 0; t < SEQ; t++) {
        const int pl = t & 1;
        float xv0 = __ldg(&g_xT[t][b0 + r0]);
        float xv1 = __ldg(&g_xT[t][b0 + r1]);
        kloop(gAr[pl], pl);
        epi(xv0, xv1, epE, gAw[1 - pl], 1 - pl, false);
        arrive();
    }

    // ---- swap to decoder B (pack in place; smB reads all done) ----
    __syncthreads();
    packB(dWhh);
    if (tid < 128) dinp[tid] = __ldg(&g_xT[SEQ - 1][b0 + tid]);
    __syncthreads();

    // ---- decoder: 24 steps ----
    #pragma unroll 1
    for (int t = 0; t < TOUT; t++) {
        const int pl = t & 1;
        kloop(gAr[pl], pl);             // wait also publishes g_part of step t-1
        if (t > 0 && tid < 128) {
            float o = fcb0;
            #pragma unroll
            for (int s2 = 0; s2 < 8; s2++)
                o += __ldcg(&g_part[(t - 1) & 1][g][s2][tid]);
            dinp[tid] = o;
            if (s == 0) out[(b0 + tid) * TOUT + (t - 1)] = o;
        }
        __syncthreads();                // dinp stable before epi reads it
        float xv0 = dinp[r0];
        float xv1 = dinp[r1];
        epi(xv0, xv1, epD, gAw[1 - pl], 1 - pl, true);
        __syncthreads();                // red complete (both n-halves)
        if (tid < 128)
            g_part[t & 1][g][s][tid] = red[tid] + red[128 + tid];
        arrive();
    }

    // ---- final output column ----
    wait_flag();
    if (tid < 128 && s == 0) {
        float o = fcb0;
        #pragma unroll
        for (int s2 = 0; s2 < 8; s2++)
            o += __ldcg(&g_part[(TOUT - 1) & 1][g][s2][tid]);
        out[(b0 + tid) * TOUT + (TOUT - 1)] = o;
    }

    // ---- reset barrier counters for next graph replay ----
    __syncthreads();
    if (tid == 0) {
        unsigned r = atomicAdd(&g_rst[g][0], 1u);
        if (r == 7u) {
            g_bar[g][0] = 0u;
            g_rst[g][0] = 0u;
            __threadfence();
        }
    }
}

extern "C" void kernel_launch(void* const* d_in, const int* in_sizes, int n_in,
                              void* d_out, int out_size) {
    (void)in_sizes; (void)n_in; (void)out_size;
    const float* x    = (const float*)d_in[0];
    const float* eWih = (const float*)d_in[1];
    const float* eWhh = (const float*)d_in[2];
    const float* ebih = (const float*)d_in[3];
    const float* ebhh = (const float*)d_in[4];
    const float* dWih = (const float*)d_in[5];
    const float* dWhh = (const float*)d_in[6];
    const float* dbih = (const float*)d_in[7];
    const float* dbhh = (const float*)d_in[8];
    const float* fcW  = (const float*)d_in[9];
    const float* fcb  = (const float*)d_in[10];

    cudaFuncSetAttribute(rnn_kernel, cudaFuncAttributeMaxDynamicSharedMemorySize, SMEM_SZ);

    transpose_x<<<dim3(BATCH / 32, SEQ / 32), dim3(32, 8)>>>(x);
    rnn_kernel<<<GRID, NTHR, SMEM_SZ>>>(eWhh, dWhh, eWih, ebih, ebhh,
                                        dWih, dbih, dbhh,
                                        fcW, fcb, (float*)d_out);
}